// round 6
// baseline (speedup 1.0000x reference)
#include <cuda_runtime.h>

// Problem constants
constexpr int Pn   = 48 * 48;   // 2304 spatial positions
constexpr int CX_  = 512;
constexpr int CF_  = 256;
constexpr int HID_ = 256;
constexpr int OUT_ = 512;
constexpr int B_   = 4;
constexpr int N_   = 4;
constexpr int BN_  = B_ * N_;   // 16

// Scratch (device globals: allocation inside kernel_launch is forbidden)
__device__ float g_Q1[(size_t)BN_ * HID_ * Pn];   //  37.7 MB
__device__ float g_K1[(size_t)B_  * HID_ * Pn];   //   9.4 MB (per-b: flow broadcast over n)
__device__ float g_Q2[(size_t)B_  * HID_ * Pn];   //   9.4 MB
__device__ float g_K2[(size_t)BN_ * HID_ * Pn];   //  37.7 MB
__device__ float g_S [(size_t)BN_ * Pn * Pn];     // 339.7 MB (scores/attn, reused by both layers)
__device__ float g_WR[(size_t)BN_ * CF_ * Pn];    //  37.7 MB
__device__ float g_WL[(size_t)BN_ * CX_ * Pn];    //  75.5 MB

// ---------------------------------------------------------------------------
// Batched SGEMM: C[z] = op(A[z]) * op(B[z]) (+ bias[m]) (+= existing C)
//   TRA=false: A is M x K row-major (A[m*lda+k]);  TRA=true: A is K x M (A[k*lda+m])
//   TRB=false: B is K x N row-major (B[k*ldb+n]);  TRB=true: B is N x K (B[n*ldb+k])
// Batch offsets: A += (z/dA)*sA, B += (z/dB)*sB, C += z*sC
// Requirements (all satisfied here): M,N multiples of 128; K multiple of 8;
// all leading dims multiples of 4; pointers 16B aligned.
// Tile: 128x128, TK=8, 256 threads, 8x8 per thread, double-buffered smem.
// ---------------------------------------------------------------------------
template<bool TRA, bool TRB, bool BIAS, bool ACCUM>
__global__ __launch_bounds__(256, 2)
void gemm128(const float* __restrict__ Ag, int lda, long long sA, int dA,
             const float* __restrict__ Bg, int ldb, long long sB, int dB,
             const float* __restrict__ bias,
             float* __restrict__ Cg, int ldc, long long sC,
             int K)
{
    const int z = blockIdx.z;
    const float* A = Ag + (long long)(z / dA) * sA;
    const float* B = Bg + (long long)(z / dB) * sB;
    float* C = Cg + (long long)z * sC;

    __shared__ float As[2][8][132];   // padded to 132 to dodge bank conflicts
    __shared__ float Bs[2][8][132];

    const int tid = threadIdx.x;
    const int tx  = tid & 15;
    const int ty  = tid >> 4;
    const int m0  = blockIdx.y * 128;
    const int n0  = blockIdx.x * 128;

    // loader index sets
    const int krow  = tid >> 5;          // 0..7   (direct: 8 k-rows x 128 contiguous)
    const int kcol4 = (tid & 31) << 2;   // 0..124
    const int arow  = tid >> 1;          // 0..127 (transpose-on-load: 128 rows x 8 k)
    const int acol4 = (tid & 1) << 2;    // 0 or 4

    float acc[8][8];
    #pragma unroll
    for (int i = 0; i < 8; ++i)
        #pragma unroll
        for (int j = 0; j < 8; ++j)
            acc[i][j] = 0.0f;

    auto loadA = [&](int kt, int buf) {
        if (TRA) {
            // A stored K x M: row k, 128 contiguous m -> float4 direct
            float4 v = *reinterpret_cast<const float4*>(
                A + (size_t)(kt * 8 + krow) * lda + m0 + kcol4);
            *reinterpret_cast<float4*>(&As[buf][krow][kcol4]) = v;
        } else {
            // A stored M x K: read 8 k's per m-row, scatter-transpose
            float4 v = *reinterpret_cast<const float4*>(
                A + (size_t)(m0 + arow) * lda + kt * 8 + acol4);
            As[buf][acol4 + 0][arow] = v.x;
            As[buf][acol4 + 1][arow] = v.y;
            As[buf][acol4 + 2][arow] = v.z;
            As[buf][acol4 + 3][arow] = v.w;
        }
    };
    auto loadB = [&](int kt, int buf) {
        if (!TRB) {
            float4 v = *reinterpret_cast<const float4*>(
                B + (size_t)(kt * 8 + krow) * ldb + n0 + kcol4);
            *reinterpret_cast<float4*>(&Bs[buf][krow][kcol4]) = v;
        } else {
            float4 v = *reinterpret_cast<const float4*>(
                B + (size_t)(n0 + arow) * ldb + kt * 8 + acol4);
            Bs[buf][acol4 + 0][arow] = v.x;
            Bs[buf][acol4 + 1][arow] = v.y;
            Bs[buf][acol4 + 2][arow] = v.z;
            Bs[buf][acol4 + 3][arow] = v.w;
        }
    };

    loadA(0, 0);
    loadB(0, 0);
    __syncthreads();

    const int nkt = K >> 3;
    for (int kt = 0; kt < nkt; ++kt) {
        const int cur = kt & 1;
        if (kt + 1 < nkt) {            // prefetch next tile into the other buffer
            loadA(kt + 1, cur ^ 1);
            loadB(kt + 1, cur ^ 1);
        }
        #pragma unroll
        for (int kk = 0; kk < 8; ++kk) {
            float4 a0 = *reinterpret_cast<const float4*>(&As[cur][kk][ty << 2]);
            float4 a1 = *reinterpret_cast<const float4*>(&As[cur][kk][64 + (ty << 2)]);
            float4 b0 = *reinterpret_cast<const float4*>(&Bs[cur][kk][tx << 2]);
            float4 b1 = *reinterpret_cast<const float4*>(&Bs[cur][kk][64 + (tx << 2)]);
            float a[8] = {a0.x, a0.y, a0.z, a0.w, a1.x, a1.y, a1.z, a1.w};
            float b[8] = {b0.x, b0.y, b0.z, b0.w, b1.x, b1.y, b1.z, b1.w};
            #pragma unroll
            for (int i = 0; i < 8; ++i)
                #pragma unroll
                for (int j = 0; j < 8; ++j)
                    acc[i][j] = fmaf(a[i], b[j], acc[i][j]);
        }
        __syncthreads();
    }

    // epilogue
    #pragma unroll
    for (int i = 0; i < 8; ++i) {
        const int m = m0 + ((i < 4) ? (ty * 4 + i) : (64 + ty * 4 + i - 4));
        const float bv = BIAS ? bias[m] : 0.0f;
        float* crow = C + (size_t)m * ldc + n0;
        float4 v0 = make_float4(acc[i][0] + bv, acc[i][1] + bv,
                                acc[i][2] + bv, acc[i][3] + bv);
        float4 v1 = make_float4(acc[i][4] + bv, acc[i][5] + bv,
                                acc[i][6] + bv, acc[i][7] + bv);
        if (ACCUM) {
            float4 o0 = *reinterpret_cast<const float4*>(crow + (tx << 2));
            float4 o1 = *reinterpret_cast<const float4*>(crow + 64 + (tx << 2));
            v0.x += o0.x; v0.y += o0.y; v0.z += o0.z; v0.w += o0.w;
            v1.x += o1.x; v1.y += o1.y; v1.z += o1.z; v1.w += o1.w;
        }
        *reinterpret_cast<float4*>(crow + (tx << 2)) = v0;
        *reinterpret_cast<float4*>(crow + 64 + (tx << 2)) = v1;
    }
}

// ---------------------------------------------------------------------------
// Row softmax over g_S: grid (Pn, BN_), 256 threads, row kept in registers
// (Pn = 2304 = 9 * 256 exactly)
// ---------------------------------------------------------------------------
__global__ __launch_bounds__(256)
void softmax_rows(float* __restrict__ S)
{
    const int tid = threadIdx.x;
    const size_t base = ((size_t)blockIdx.y * Pn + blockIdx.x) * Pn;

    float r[9];
    float mx = -3.4e38f;
    #pragma unroll
    for (int j = 0; j < 9; ++j) {
        r[j] = S[base + tid + j * 256];
        mx = fmaxf(mx, r[j]);
    }

    __shared__ float sred[8];
    #pragma unroll
    for (int o = 16; o > 0; o >>= 1)
        mx = fmaxf(mx, __shfl_xor_sync(0xffffffffu, mx, o));
    if ((tid & 31) == 0) sred[tid >> 5] = mx;
    __syncthreads();
    mx = sred[0];
    #pragma unroll
    for (int w = 1; w < 8; ++w) mx = fmaxf(mx, sred[w]);

    float s = 0.0f;
    #pragma unroll
    for (int j = 0; j < 9; ++j) {
        r[j] = __expf(r[j] - mx);
        s += r[j];
    }
    #pragma unroll
    for (int o = 16; o > 0; o >>= 1)
        s += __shfl_xor_sync(0xffffffffu, s, o);
    __syncthreads();
    if ((tid & 31) == 0) sred[tid >> 5] = s;
    __syncthreads();
    s = 0.0f;
    #pragma unroll
    for (int w = 0; w < 8; ++w) s += sred[w];

    const float inv = 1.0f / s;
    #pragma unroll
    for (int j = 0; j < 9; ++j)
        S[base + tid + j * 256] = r[j] * inv;
}

// ---------------------------------------------------------------------------
// Launch sequence (all on default stream => serialized, graph-capturable)
// ---------------------------------------------------------------------------
extern "C" void kernel_launch(void* const* d_in, const int* in_sizes, int n_in,
                              void* d_out, int out_size)
{
    const float* mv  = (const float*)d_in[0];   // [4,4,512,48,48] -> [16,512,P]
    const float* ff  = (const float*)d_in[1];   // [4,256,48,48]   -> [4,256,P]
    const float* wq1 = (const float*)d_in[2];
    const float* bq1 = (const float*)d_in[3];
    const float* wk1 = (const float*)d_in[4];
    const float* bk1 = (const float*)d_in[5];
    const float* wq2 = (const float*)d_in[6];
    const float* bq2 = (const float*)d_in[7];
    const float* wk2 = (const float*)d_in[8];
    const float* bk2 = (const float*)d_in[9];
    const float* wdr = (const float*)d_in[10];  // [512, 1536]
    const float* bdr = (const float*)d_in[11];
    float* out = (float*)d_out;                 // [16, 512, P]

    float *Q1, *K1, *Q2, *K2, *S, *WR, *WL;
    cudaGetSymbolAddress((void**)&Q1, g_Q1);
    cudaGetSymbolAddress((void**)&K1, g_K1);
    cudaGetSymbolAddress((void**)&Q2, g_Q2);
    cudaGetSymbolAddress((void**)&K2, g_K2);
    cudaGetSymbolAddress((void**)&S,  g_S);
    cudaGetSymbolAddress((void**)&WR, g_WR);
    cudaGetSymbolAddress((void**)&WL, g_WL);

    const long long sMV = (long long)CX_  * Pn;   // per-image memory slice
    const long long sFF = (long long)CF_  * Pn;   // per-b flow slice
    const long long sH  = (long long)HID_ * Pn;
    const long long sS  = (long long)Pn   * Pn;
    const long long sWR = (long long)CF_  * Pn;
    const long long sWL = (long long)CX_  * Pn;
    const long long sO  = (long long)OUT_ * Pn;

    // --- projections ---
    // Q1[z] = wq1 @ mv[z] + bq1            [256 x P], K=512, batch 16
    gemm128<false, false, true, false><<<dim3(18, 2, 16), 256>>>(
        wq1, CX_, 0LL, 1,  mv, Pn, sMV, 1,  bq1,  Q1, Pn, sH, CX_);
    // K1[b] = wk1 @ ff[b] + bk1            [256 x P], K=256, batch 4 (per-b only)
    gemm128<false, false, true, false><<<dim3(18, 2, 4), 256>>>(
        wk1, CF_, 0LL, 1,  ff, Pn, sFF, 1,  bk1,  K1, Pn, sH, CF_);
    // Q2[b] = wq2 @ ff[b] + bq2            [256 x P], K=256, batch 4
    gemm128<false, false, true, false><<<dim3(18, 2, 4), 256>>>(
        wq2, CF_, 0LL, 1,  ff, Pn, sFF, 1,  bq2,  Q2, Pn, sH, CF_);
    // K2[z] = wk2 @ mv[z] + bk2            [256 x P], K=512, batch 16
    gemm128<false, false, true, false><<<dim3(18, 2, 16), 256>>>(
        wk2, CX_, 0LL, 1,  mv, Pn, sMV, 1,  bk2,  K2, Pn, sH, CX_);

    // --- layer 1: scores = Q1^T K1 ; softmax ; WR = ff @ attn^T ---
    gemm128<true, false, false, false><<<dim3(18, 18, 16), 256>>>(
        Q1, Pn, sH, 1,  K1, Pn, sH, 4,  nullptr,  S, Pn, sS, HID_);
    softmax_rows<<<dim3(Pn, BN_), 256>>>(S);
    gemm128<false, true, false, false><<<dim3(18, 2, 16), 256>>>(
        ff, Pn, sFF, 4,  S, Pn, sS, 1,  nullptr,  WR, Pn, sWR, Pn);

    // --- layer 2: scores = Q2^T K2 ; softmax ; WL = mv @ attn^T ---
    gemm128<true, false, false, false><<<dim3(18, 18, 16), 256>>>(
        Q2, Pn, sH, 4,  K2, Pn, sH, 1,  nullptr,  S, Pn, sS, HID_);
    softmax_rows<<<dim3(Pn, BN_), 256>>>(S);
    gemm128<false, true, false, false><<<dim3(18, 4, 16), 256>>>(
        mv, Pn, sMV, 1,  S, Pn, sS, 1,  nullptr,  WL, Pn, sWL, Pn);

    // --- final 1x1 conv: out = wdr @ concat(mv, WL, ff, WR) + bdr ---
    // split into 4 accumulating GEMMs over the concat slices of wdr (ld = 1536)
    gemm128<false, false, true, false><<<dim3(18, 4, 16), 256>>>(
        wdr + 0,    2 * (CX_ + CF_), 0LL, 1,  mv, Pn, sMV, 1,  bdr,
        out, Pn, sO, CX_);
    gemm128<false, false, false, true><<<dim3(18, 4, 16), 256>>>(
        wdr + 512,  2 * (CX_ + CF_), 0LL, 1,  WL, Pn, sWL, 1,  nullptr,
        out, Pn, sO, CX_);
    gemm128<false, false, false, true><<<dim3(18, 4, 16), 256>>>(
        wdr + 1024, 2 * (CX_ + CF_), 0LL, 1,  ff, Pn, sFF, 4,  nullptr,
        out, Pn, sO, CF_);
    gemm128<false, false, false, true><<<dim3(18, 4, 16), 256>>>(
        wdr + 1280, 2 * (CX_ + CF_), 0LL, 1,  WR, Pn, sWR, 1,  nullptr,
        out, Pn, sO, CF_);
}

// round 7
// speedup vs baseline: 1.0004x; 1.0004x over previous
#include <cuda_runtime.h>

// Problem constants
constexpr int Pn   = 48 * 48;   // 2304 spatial positions
constexpr int CX_  = 512;
constexpr int CF_  = 256;
constexpr int HID_ = 256;
constexpr int OUT_ = 512;
constexpr int B_   = 4;
constexpr int N_   = 4;
constexpr int BN_  = B_ * N_;   // 16

// Scratch (device globals: allocation inside kernel_launch is forbidden)
__device__ float g_Q1[(size_t)BN_ * HID_ * Pn];   //  37.7 MB
__device__ float g_K1[(size_t)B_  * HID_ * Pn];   //   9.4 MB (per-b: flow broadcast over n)
__device__ float g_Q2[(size_t)B_  * HID_ * Pn];   //   9.4 MB
__device__ float g_K2[(size_t)BN_ * HID_ * Pn];   //  37.7 MB
__device__ float g_S [(size_t)BN_ * Pn * Pn];     // 339.7 MB (scores/attn, reused by both layers)
__device__ float g_WR[(size_t)BN_ * CF_ * Pn];    //  37.7 MB
__device__ float g_WL[(size_t)BN_ * CX_ * Pn];    //  75.5 MB

// ---------------------------------------------------------------------------
// Batched SGEMM: C[z] = op(A[z]) * op(B[z]) (+ bias[m]) (+= existing C)
//   TRA=false: A is M x K row-major (A[m*lda+k]);  TRA=true: A is K x M (A[k*lda+m])
//   TRB=false: B is K x N row-major (B[k*ldb+n]);  TRB=true: B is N x K (B[n*ldb+k])
// Batch offsets: A += (z/dA)*sA, B += (z/dB)*sB, C += z*sC
// Requirements (all satisfied here): M,N multiples of 128; K multiple of 8;
// all leading dims multiples of 4; pointers 16B aligned.
// Tile: 128x128, TK=8, 256 threads, 8x8 per thread, double-buffered smem.
// ---------------------------------------------------------------------------
template<bool TRA, bool TRB, bool BIAS, bool ACCUM>
__global__ __launch_bounds__(256, 2)
void gemm128(const float* __restrict__ Ag, int lda, long long sA, int dA,
             const float* __restrict__ Bg, int ldb, long long sB, int dB,
             const float* __restrict__ bias,
             float* __restrict__ Cg, int ldc, long long sC,
             int K)
{
    const int z = blockIdx.z;
    const float* A = Ag + (long long)(z / dA) * sA;
    const float* B = Bg + (long long)(z / dB) * sB;
    float* C = Cg + (long long)z * sC;

    __shared__ float As[2][8][132];   // padded to 132 to dodge bank conflicts
    __shared__ float Bs[2][8][132];

    const int tid = threadIdx.x;
    const int tx  = tid & 15;
    const int ty  = tid >> 4;
    const int m0  = blockIdx.y * 128;
    const int n0  = blockIdx.x * 128;

    // loader index sets
    const int krow  = tid >> 5;          // 0..7   (direct: 8 k-rows x 128 contiguous)
    const int kcol4 = (tid & 31) << 2;   // 0..124
    const int arow  = tid >> 1;          // 0..127 (transpose-on-load: 128 rows x 8 k)
    const int acol4 = (tid & 1) << 2;    // 0 or 4

    float acc[8][8];
    #pragma unroll
    for (int i = 0; i < 8; ++i)
        #pragma unroll
        for (int j = 0; j < 8; ++j)
            acc[i][j] = 0.0f;

    auto loadA = [&](int kt, int buf) {
        if (TRA) {
            // A stored K x M: row k, 128 contiguous m -> float4 direct
            float4 v = *reinterpret_cast<const float4*>(
                A + (size_t)(kt * 8 + krow) * lda + m0 + kcol4);
            *reinterpret_cast<float4*>(&As[buf][krow][kcol4]) = v;
        } else {
            // A stored M x K: read 8 k's per m-row, scatter-transpose
            float4 v = *reinterpret_cast<const float4*>(
                A + (size_t)(m0 + arow) * lda + kt * 8 + acol4);
            As[buf][acol4 + 0][arow] = v.x;
            As[buf][acol4 + 1][arow] = v.y;
            As[buf][acol4 + 2][arow] = v.z;
            As[buf][acol4 + 3][arow] = v.w;
        }
    };
    auto loadB = [&](int kt, int buf) {
        if (!TRB) {
            float4 v = *reinterpret_cast<const float4*>(
                B + (size_t)(kt * 8 + krow) * ldb + n0 + kcol4);
            *reinterpret_cast<float4*>(&Bs[buf][krow][kcol4]) = v;
        } else {
            float4 v = *reinterpret_cast<const float4*>(
                B + (size_t)(n0 + arow) * ldb + kt * 8 + acol4);
            Bs[buf][acol4 + 0][arow] = v.x;
            Bs[buf][acol4 + 1][arow] = v.y;
            Bs[buf][acol4 + 2][arow] = v.z;
            Bs[buf][acol4 + 3][arow] = v.w;
        }
    };

    loadA(0, 0);
    loadB(0, 0);
    __syncthreads();

    const int nkt = K >> 3;
    for (int kt = 0; kt < nkt; ++kt) {
        const int cur = kt & 1;
        if (kt + 1 < nkt) {            // prefetch next tile into the other buffer
            loadA(kt + 1, cur ^ 1);
            loadB(kt + 1, cur ^ 1);
        }
        #pragma unroll
        for (int kk = 0; kk < 8; ++kk) {
            float4 a0 = *reinterpret_cast<const float4*>(&As[cur][kk][ty << 2]);
            float4 a1 = *reinterpret_cast<const float4*>(&As[cur][kk][64 + (ty << 2)]);
            float4 b0 = *reinterpret_cast<const float4*>(&Bs[cur][kk][tx << 2]);
            float4 b1 = *reinterpret_cast<const float4*>(&Bs[cur][kk][64 + (tx << 2)]);
            float a[8] = {a0.x, a0.y, a0.z, a0.w, a1.x, a1.y, a1.z, a1.w};
            float b[8] = {b0.x, b0.y, b0.z, b0.w, b1.x, b1.y, b1.z, b1.w};
            #pragma unroll
            for (int i = 0; i < 8; ++i)
                #pragma unroll
                for (int j = 0; j < 8; ++j)
                    acc[i][j] = fmaf(a[i], b[j], acc[i][j]);
        }
        __syncthreads();
    }

    // epilogue
    #pragma unroll
    for (int i = 0; i < 8; ++i) {
        const int m = m0 + ((i < 4) ? (ty * 4 + i) : (64 + ty * 4 + i - 4));
        const float bv = BIAS ? bias[m] : 0.0f;
        float* crow = C + (size_t)m * ldc + n0;
        float4 v0 = make_float4(acc[i][0] + bv, acc[i][1] + bv,
                                acc[i][2] + bv, acc[i][3] + bv);
        float4 v1 = make_float4(acc[i][4] + bv, acc[i][5] + bv,
                                acc[i][6] + bv, acc[i][7] + bv);
        if (ACCUM) {
            float4 o0 = *reinterpret_cast<const float4*>(crow + (tx << 2));
            float4 o1 = *reinterpret_cast<const float4*>(crow + 64 + (tx << 2));
            v0.x += o0.x; v0.y += o0.y; v0.z += o0.z; v0.w += o0.w;
            v1.x += o1.x; v1.y += o1.y; v1.z += o1.z; v1.w += o1.w;
        }
        *reinterpret_cast<float4*>(crow + (tx << 2)) = v0;
        *reinterpret_cast<float4*>(crow + 64 + (tx << 2)) = v1;
    }
}

// ---------------------------------------------------------------------------
// Row softmax over g_S: grid (Pn, BN_), 256 threads, row kept in registers
// (Pn = 2304 = 9 * 256 exactly)
// ---------------------------------------------------------------------------
__global__ __launch_bounds__(256)
void softmax_rows(float* __restrict__ S)
{
    const int tid = threadIdx.x;
    const size_t base = ((size_t)blockIdx.y * Pn + blockIdx.x) * Pn;

    float r[9];
    float mx = -3.4e38f;
    #pragma unroll
    for (int j = 0; j < 9; ++j) {
        r[j] = S[base + tid + j * 256];
        mx = fmaxf(mx, r[j]);
    }

    __shared__ float sred[8];
    #pragma unroll
    for (int o = 16; o > 0; o >>= 1)
        mx = fmaxf(mx, __shfl_xor_sync(0xffffffffu, mx, o));
    if ((tid & 31) == 0) sred[tid >> 5] = mx;
    __syncthreads();
    mx = sred[0];
    #pragma unroll
    for (int w = 1; w < 8; ++w) mx = fmaxf(mx, sred[w]);

    float s = 0.0f;
    #pragma unroll
    for (int j = 0; j < 9; ++j) {
        r[j] = __expf(r[j] - mx);
        s += r[j];
    }
    #pragma unroll
    for (int o = 16; o > 0; o >>= 1)
        s += __shfl_xor_sync(0xffffffffu, s, o);
    __syncthreads();
    if ((tid & 31) == 0) sred[tid >> 5] = s;
    __syncthreads();
    s = 0.0f;
    #pragma unroll
    for (int w = 0; w < 8; ++w) s += sred[w];

    const float inv = 1.0f / s;
    #pragma unroll
    for (int j = 0; j < 9; ++j)
        S[base + tid + j * 256] = r[j] * inv;
}

// ---------------------------------------------------------------------------
// Launch sequence (all on default stream => serialized, graph-capturable)
// ---------------------------------------------------------------------------
extern "C" void kernel_launch(void* const* d_in, const int* in_sizes, int n_in,
                              void* d_out, int out_size)
{
    const float* mv  = (const float*)d_in[0];   // [4,4,512,48,48] -> [16,512,P]
    const float* ff  = (const float*)d_in[1];   // [4,256,48,48]   -> [4,256,P]
    const float* wq1 = (const float*)d_in[2];
    const float* bq1 = (const float*)d_in[3];
    const float* wk1 = (const float*)d_in[4];
    const float* bk1 = (const float*)d_in[5];
    const float* wq2 = (const float*)d_in[6];
    const float* bq2 = (const float*)d_in[7];
    const float* wk2 = (const float*)d_in[8];
    const float* bk2 = (const float*)d_in[9];
    const float* wdr = (const float*)d_in[10];  // [512, 1536]
    const float* bdr = (const float*)d_in[11];
    float* out = (float*)d_out;                 // [16, 512, P]

    float *Q1, *K1, *Q2, *K2, *S, *WR, *WL;
    cudaGetSymbolAddress((void**)&Q1, g_Q1);
    cudaGetSymbolAddress((void**)&K1, g_K1);
    cudaGetSymbolAddress((void**)&Q2, g_Q2);
    cudaGetSymbolAddress((void**)&K2, g_K2);
    cudaGetSymbolAddress((void**)&S,  g_S);
    cudaGetSymbolAddress((void**)&WR, g_WR);
    cudaGetSymbolAddress((void**)&WL, g_WL);

    const long long sMV = (long long)CX_  * Pn;   // per-image memory slice
    const long long sFF = (long long)CF_  * Pn;   // per-b flow slice
    const long long sH  = (long long)HID_ * Pn;
    const long long sS  = (long long)Pn   * Pn;
    const long long sWR = (long long)CF_  * Pn;
    const long long sWL = (long long)CX_  * Pn;
    const long long sO  = (long long)OUT_ * Pn;

    // --- projections ---
    // Q1[z] = wq1 @ mv[z] + bq1            [256 x P], K=512, batch 16
    gemm128<false, false, true, false><<<dim3(18, 2, 16), 256>>>(
        wq1, CX_, 0LL, 1,  mv, Pn, sMV, 1,  bq1,  Q1, Pn, sH, CX_);
    // K1[b] = wk1 @ ff[b] + bk1            [256 x P], K=256, batch 4 (per-b only)
    gemm128<false, false, true, false><<<dim3(18, 2, 4), 256>>>(
        wk1, CF_, 0LL, 1,  ff, Pn, sFF, 1,  bk1,  K1, Pn, sH, CF_);
    // Q2[b] = wq2 @ ff[b] + bq2            [256 x P], K=256, batch 4
    gemm128<false, false, true, false><<<dim3(18, 2, 4), 256>>>(
        wq2, CF_, 0LL, 1,  ff, Pn, sFF, 1,  bq2,  Q2, Pn, sH, CF_);
    // K2[z] = wk2 @ mv[z] + bk2            [256 x P], K=512, batch 16
    gemm128<false, false, true, false><<<dim3(18, 2, 16), 256>>>(
        wk2, CX_, 0LL, 1,  mv, Pn, sMV, 1,  bk2,  K2, Pn, sH, CX_);

    // --- layer 1: scores = Q1^T K1 ; softmax ; WR = ff @ attn^T ---
    gemm128<true, false, false, false><<<dim3(18, 18, 16), 256>>>(
        Q1, Pn, sH, 1,  K1, Pn, sH, 4,  nullptr,  S, Pn, sS, HID_);
    softmax_rows<<<dim3(Pn, BN_), 256>>>(S);
    gemm128<false, true, false, false><<<dim3(18, 2, 16), 256>>>(
        ff, Pn, sFF, 4,  S, Pn, sS, 1,  nullptr,  WR, Pn, sWR, Pn);

    // --- layer 2: scores = Q2^T K2 ; softmax ; WL = mv @ attn^T ---
    gemm128<true, false, false, false><<<dim3(18, 18, 16), 256>>>(
        Q2, Pn, sH, 4,  K2, Pn, sH, 1,  nullptr,  S, Pn, sS, HID_);
    softmax_rows<<<dim3(Pn, BN_), 256>>>(S);
    gemm128<false, true, false, false><<<dim3(18, 4, 16), 256>>>(
        mv, Pn, sMV, 1,  S, Pn, sS, 1,  nullptr,  WL, Pn, sWL, Pn);

    // --- final 1x1 conv: out = wdr @ concat(mv, WL, ff, WR) + bdr ---
    // split into 4 accumulating GEMMs over the concat slices of wdr (ld = 1536)
    gemm128<false, false, true, false><<<dim3(18, 4, 16), 256>>>(
        wdr + 0,    2 * (CX_ + CF_), 0LL, 1,  mv, Pn, sMV, 1,  bdr,
        out, Pn, sO, CX_);
    gemm128<false, false, false, true><<<dim3(18, 4, 16), 256>>>(
        wdr + 512,  2 * (CX_ + CF_), 0LL, 1,  WL, Pn, sWL, 1,  nullptr,
        out, Pn, sO, CX_);
    gemm128<false, false, false, true><<<dim3(18, 4, 16), 256>>>(
        wdr + 1024, 2 * (CX_ + CF_), 0LL, 1,  ff, Pn, sFF, 4,  nullptr,
        out, Pn, sO, CF_);
    gemm128<false, false, false, true><<<dim3(18, 4, 16), 256>>>(
        wdr + 1280, 2 * (CX_ + CF_), 0LL, 1,  WR, Pn, sWR, 1,  nullptr,
        out, Pn, sO, CF_);
}